// round 1
// baseline (speedup 1.0000x reference)
#include <cuda_runtime.h>

// Problem shape (fixed by dataset)
#define BATCH 2
#define HEADS 16
#define SEQ   2048
#define DHEAD 64
#define NHEADS (BATCH*HEADS)          // 32
#define ELEMS  (NHEADS*SEQ*DHEAD)     // 4194304

// Tiling
#define BM 128
#define BN 64
#define THREADS 256
#define STRIDE 68   // 64 + 4 pad, keeps float4 alignment per row

// RoPE'd Q and K scratch (static device arrays: allowed, no runtime alloc)
__device__ float g_Qr[ELEMS];
__device__ float g_Kr[ELEMS];

// ---------------------------------------------------------------------------
// RoPE precompute: rotate (even,odd) pairs of Q and K, write to scratch.
// idx enumerates pairs: t = pair index in head dim (0..31), s = seq pos.
// ---------------------------------------------------------------------------
__global__ void rope_kernel(const float* __restrict__ Q,
                            const float* __restrict__ K,
                            int total_pairs) {
    int idx = blockIdx.x * blockDim.x + threadIdx.x;
    if (idx >= total_pairs) return;
    int t = idx & 31;
    int s = (idx >> 5) & (SEQ - 1);

    // div = exp(2t * (-ln(10000)/64)), fp32 like the reference
    float div = expf((float)(2 * t) * (-9.210340371976184f / 64.0f));
    float ang = (float)s * div;
    float sn, cs;
    sincosf(ang, &sn, &cs);

    float2 q2 = ((const float2*)Q)[idx];
    float2 k2 = ((const float2*)K)[idx];
    float2 qo, ko;
    qo.x = q2.x * cs - q2.y * sn;
    qo.y = q2.x * sn + q2.y * cs;
    ko.x = k2.x * cs - k2.y * sn;
    ko.y = k2.x * sn + k2.y * cs;
    ((float2*)g_Qr)[idx] = qo;
    ((float2*)g_Kr)[idx] = ko;
}

// ---------------------------------------------------------------------------
// Flash attention (causal, no scale factor — reference has none), fp32.
// Grid: x = SEQ/BM (processed in reverse so heavy blocks start first),
//       y = B*H.
// 256 threads as 16x16; each thread owns an 8-row x 4-col micro-tile.
// ---------------------------------------------------------------------------
__global__ __launch_bounds__(THREADS, 2)
void attn_kernel(const float* __restrict__ V, float* __restrict__ O) {
    extern __shared__ float smem[];
    float* sQ  = smem;                    // BM x STRIDE   (row-major, d along row)
    float* sKT = sQ  + BM * STRIDE;       // DHEAD x STRIDE (k-major: sKT[k][n] = K[n][k])
    float* sV  = sKT + DHEAD * STRIDE;    // BN x STRIDE   (row-major, d along row)
    float* sP  = sV  + BN * STRIDE;       // BM x STRIDE

    const int qb = gridDim.x - 1 - blockIdx.x;   // heavy tiles first
    const int bh = blockIdx.y;
    const int q0 = qb * BM;

    const float* Qr = g_Qr + (size_t)bh * SEQ * DHEAD;
    const float* Kr = g_Kr + (size_t)bh * SEQ * DHEAD;
    const float* Vh = V    + (size_t)bh * SEQ * DHEAD;
    float*       Oh = O    + (size_t)bh * SEQ * DHEAD;

    const int tid  = threadIdx.x;
    const int ty   = tid >> 4;        // 0..15
    const int tx   = tid & 15;        // 0..15
    const int row0 = ty * 8;
    const int col0 = tx * 4;

    // Load Q tile (BM x 64) as float4
    for (int i = tid; i < BM * 16; i += THREADS) {
        int r  = i >> 4;
        int c4 = i & 15;
        float4 v = ((const float4*)(Qr + (size_t)(q0 + r) * DHEAD))[c4];
        *((float4*)&sQ[r * STRIDE + c4 * 4]) = v;
    }

    float m_i[8], l_i[8], acc[8][4];
#pragma unroll
    for (int i = 0; i < 8; i++) {
        m_i[i] = -3.0e38f;
        l_i[i] = 0.0f;
#pragma unroll
        for (int j = 0; j < 4; j++) acc[i][j] = 0.0f;
    }

    const int ntiles = (q0 + BM) / BN;   // key tiles 0 .. ntiles-1

    for (int kb = 0; kb < ntiles; kb++) {
        const int n0 = kb * BN;

        __syncthreads();   // previous PV / loads done before overwriting K,V

        // Load K (transposed into sKT) and V, both as float4 from global
        for (int i = tid; i < BN * 16; i += THREADS) {
            int r  = i >> 4;
            int c4 = i & 15;
            float4 kv = ((const float4*)(Kr + (size_t)(n0 + r) * DHEAD))[c4];
            sKT[(c4 * 4 + 0) * STRIDE + r] = kv.x;
            sKT[(c4 * 4 + 1) * STRIDE + r] = kv.y;
            sKT[(c4 * 4 + 2) * STRIDE + r] = kv.z;
            sKT[(c4 * 4 + 3) * STRIDE + r] = kv.w;
            float4 vv = ((const float4*)(Vh + (size_t)(n0 + r) * DHEAD))[c4];
            *((float4*)&sV[r * STRIDE + c4 * 4]) = vv;
        }
        __syncthreads();

        // ---- S = Q K^T (8x4 per thread) ----
        float s[8][4];
#pragma unroll
        for (int i = 0; i < 8; i++)
#pragma unroll
            for (int j = 0; j < 4; j++) s[i][j] = 0.0f;

#pragma unroll 4
        for (int k = 0; k < DHEAD; k += 4) {
            float4 kf0 = *((float4*)&sKT[(k + 0) * STRIDE + col0]);
            float4 kf1 = *((float4*)&sKT[(k + 1) * STRIDE + col0]);
            float4 kf2 = *((float4*)&sKT[(k + 2) * STRIDE + col0]);
            float4 kf3 = *((float4*)&sKT[(k + 3) * STRIDE + col0]);
#pragma unroll
            for (int i = 0; i < 8; i++) {
                float4 qf = *((float4*)&sQ[(row0 + i) * STRIDE + k]);
                s[i][0] += qf.x * kf0.x + qf.y * kf1.x + qf.z * kf2.x + qf.w * kf3.x;
                s[i][1] += qf.x * kf0.y + qf.y * kf1.y + qf.z * kf2.y + qf.w * kf3.y;
                s[i][2] += qf.x * kf0.z + qf.y * kf1.z + qf.z * kf2.z + qf.w * kf3.z;
                s[i][3] += qf.x * kf0.w + qf.y * kf1.w + qf.z * kf2.w + qf.w * kf3.w;
            }
        }

        // Causal mask: only the last two key tiles intersect the diagonal
        if (kb >= ntiles - 2) {
            const int qbase = q0 + row0;
            const int kbase = n0 + col0;
#pragma unroll
            for (int i = 0; i < 8; i++)
#pragma unroll
                for (int j = 0; j < 4; j++)
                    if (kbase + j > qbase + i) s[i][j] = -3.0e38f;
        }

        // ---- Online softmax (row stats across 16-lane segments) ----
#pragma unroll
        for (int i = 0; i < 8; i++) {
            float mt = fmaxf(fmaxf(s[i][0], s[i][1]), fmaxf(s[i][2], s[i][3]));
#pragma unroll
            for (int off = 8; off >= 1; off >>= 1)
                mt = fmaxf(mt, __shfl_xor_sync(0xffffffffu, mt, off, 16));

            float mnew  = fmaxf(m_i[i], mt);
            float scale = __expf(m_i[i] - mnew);
            m_i[i] = mnew;

            float p0 = __expf(s[i][0] - mnew);
            float p1 = __expf(s[i][1] - mnew);
            float p2 = __expf(s[i][2] - mnew);
            float p3 = __expf(s[i][3] - mnew);
            float ps = (p0 + p1) + (p2 + p3);
#pragma unroll
            for (int off = 8; off >= 1; off >>= 1)
                ps += __shfl_xor_sync(0xffffffffu, ps, off, 16);

            l_i[i] = l_i[i] * scale + ps;
#pragma unroll
            for (int j = 0; j < 4; j++) acc[i][j] *= scale;

            *((float4*)&sP[(row0 + i) * STRIDE + col0]) = make_float4(p0, p1, p2, p3);
        }
        __syncthreads();

        // ---- O += P V (8x4 per thread) ----
#pragma unroll 4
        for (int n = 0; n < BN; n += 4) {
            float4 vf0 = *((float4*)&sV[(n + 0) * STRIDE + col0]);
            float4 vf1 = *((float4*)&sV[(n + 1) * STRIDE + col0]);
            float4 vf2 = *((float4*)&sV[(n + 2) * STRIDE + col0]);
            float4 vf3 = *((float4*)&sV[(n + 3) * STRIDE + col0]);
#pragma unroll
            for (int i = 0; i < 8; i++) {
                float4 pf = *((float4*)&sP[(row0 + i) * STRIDE + n]);
                acc[i][0] += pf.x * vf0.x + pf.y * vf1.x + pf.z * vf2.x + pf.w * vf3.x;
                acc[i][1] += pf.x * vf0.y + pf.y * vf1.y + pf.z * vf2.y + pf.w * vf3.y;
                acc[i][2] += pf.x * vf0.z + pf.y * vf1.z + pf.z * vf2.z + pf.w * vf3.z;
                acc[i][3] += pf.x * vf0.w + pf.y * vf1.w + pf.z * vf2.w + pf.w * vf3.w;
            }
        }
    }

    // Epilogue: normalize and store
#pragma unroll
    for (int i = 0; i < 8; i++) {
        float inv = 1.0f / l_i[i];
        float4 o;
        o.x = acc[i][0] * inv;
        o.y = acc[i][1] * inv;
        o.z = acc[i][2] * inv;
        o.w = acc[i][3] * inv;
        *((float4*)(Oh + (size_t)(q0 + row0 + i) * DHEAD + col0)) = o;
    }
}

// ---------------------------------------------------------------------------
extern "C" void kernel_launch(void* const* d_in, const int* in_sizes, int n_in,
                              void* d_out, int out_size) {
    const float* Q = (const float*)d_in[0];
    const float* K = (const float*)d_in[1];
    const float* V = (const float*)d_in[2];
    float*       O = (float*)d_out;

    // 1) RoPE precompute into device scratch
    const int total_pairs = ELEMS / 2;   // float2 pairs
    rope_kernel<<<(total_pairs + 255) / 256, 256>>>(Q, K, total_pairs);

    // 2) Flash attention
    size_t smem_bytes = (size_t)(2 * BM * STRIDE + DHEAD * STRIDE + BN * STRIDE) * sizeof(float);
    cudaFuncSetAttribute(attn_kernel, cudaFuncAttributeMaxDynamicSharedMemorySize,
                         (int)smem_bytes);
    dim3 grid(SEQ / BM, NHEADS);
    attn_kernel<<<grid, THREADS, smem_bytes>>>(V, O);
}

// round 2
// speedup vs baseline: 2.2860x; 2.2860x over previous
#include <cuda_runtime.h>
#include <cstdint>

// Problem shape (fixed by dataset)
#define BATCH 2
#define HEADS 16
#define SEQ   2048
#define DHEAD 64
#define NHEADS (BATCH*HEADS)          // 32
#define ELEMS  (NHEADS*SEQ*DHEAD)     // 4194304

// Tiling
#define BM 64
#define BN 64
#define THREADS 128
#define KSTR 68   // K smem stride (floats): 68 % 32 == 4 -> B-frag banks 4g+q, conflict-free
#define VSTR 72   // V smem stride:          72 % 32 == 8 -> B-frag banks 8q+g, conflict-free
#define PSTR 72   // P smem stride

#define LOG2E 1.4426950408889634f

// tf32 big/small splits of RoPE'd Q (pre-scaled by log2e) and K
__device__ float g_Qb[ELEMS];
__device__ float g_Qs[ELEMS];
__device__ float g_Kb[ELEMS];
__device__ float g_Ks[ELEMS];

__device__ __forceinline__ uint32_t f2tf32(float x) {
    uint32_t r;
    asm("cvt.rna.tf32.f32 %0, %1;" : "=r"(r) : "f"(x));
    return r;
}

// D += A * B, m16n8k8 tf32
__device__ __forceinline__ void mma8(float* c, const uint32_t* a, uint32_t b0, uint32_t b1) {
    asm("mma.sync.aligned.m16n8k8.row.col.f32.tf32.tf32.f32 "
        "{%0,%1,%2,%3}, {%4,%5,%6,%7}, {%8,%9}, {%0,%1,%2,%3};"
        : "+f"(c[0]), "+f"(c[1]), "+f"(c[2]), "+f"(c[3])
        : "r"(a[0]), "r"(a[1]), "r"(a[2]), "r"(a[3]), "r"(b0), "r"(b1));
}

// ---------------------------------------------------------------------------
// RoPE + log2e fold (Q only) + tf32 big/small split.
// idx enumerates (even,odd) pairs: t = pair in head dim (0..31), s = seq pos.
// ---------------------------------------------------------------------------
__global__ void rope_split_kernel(const float* __restrict__ Q,
                                  const float* __restrict__ K,
                                  int total_pairs) {
    int idx = blockIdx.x * blockDim.x + threadIdx.x;
    if (idx >= total_pairs) return;
    int t = idx & 31;
    int s = (idx >> 5) & (SEQ - 1);

    float div = expf((float)(2 * t) * (-9.210340371976184f / 64.0f));
    float ang = (float)s * div;
    float sn, cs;
    sincosf(ang, &sn, &cs);

    float2 q2 = ((const float2*)Q)[idx];
    float2 k2 = ((const float2*)K)[idx];

    float qx = (q2.x * cs - q2.y * sn) * LOG2E;
    float qy = (q2.x * sn + q2.y * cs) * LOG2E;
    float kx = k2.x * cs - k2.y * sn;
    float ky = k2.x * sn + k2.y * cs;

    uint32_t qbx = f2tf32(qx), qby = f2tf32(qy);
    uint32_t kbx = f2tf32(kx), kby = f2tf32(ky);
    float2 qb = make_float2(__uint_as_float(qbx), __uint_as_float(qby));
    float2 kb = make_float2(__uint_as_float(kbx), __uint_as_float(kby));
    float2 qs = make_float2(__uint_as_float(f2tf32(qx - qb.x)),
                            __uint_as_float(f2tf32(qy - qb.y)));
    float2 ks = make_float2(__uint_as_float(f2tf32(kx - kb.x)),
                            __uint_as_float(f2tf32(ky - kb.y)));

    ((float2*)g_Qb)[idx] = qb;
    ((float2*)g_Qs)[idx] = qs;
    ((float2*)g_Kb)[idx] = kb;
    ((float2*)g_Ks)[idx] = ks;
}

// ---------------------------------------------------------------------------
// Flash attention, tf32 tensor-core (3xTF32 for QK^T, 1xTF32 for PV).
// 4 warps; each warp owns 16 rows of the 64-row Q block.
// Scores are in log2 units (Q pre-scaled by log2e) -> exp2f softmax.
// ---------------------------------------------------------------------------
__global__ __launch_bounds__(THREADS, 2)
void attn_kernel(const float* __restrict__ V, float* __restrict__ O) {
    extern __shared__ float smem[];
    float* sKb = smem;                     // [64][KSTR]
    float* sKs = sKb + BN * KSTR;          // [64][KSTR]
    float* sV  = sKs + BN * KSTR;          // [64][VSTR]  (key-major: [key][d])
    float* sP  = sV  + BN * VSTR;          // 4 x [16][PSTR], per-warp

    const int qblk = gridDim.x - 1 - blockIdx.x;   // heavy blocks first
    const int bh   = blockIdx.y;
    const int q0   = qblk * BM;

    const float* Qbg = g_Qb + (size_t)bh * SEQ * DHEAD;
    const float* Qsg = g_Qs + (size_t)bh * SEQ * DHEAD;
    const float* Kbg = g_Kb + (size_t)bh * SEQ * DHEAD;
    const float* Ksg = g_Ks + (size_t)bh * SEQ * DHEAD;
    const float* Vh  = V    + (size_t)bh * SEQ * DHEAD;
    float*       Oh  = O    + (size_t)bh * SEQ * DHEAD;

    const int tid  = threadIdx.x;
    const int wid  = tid >> 5;
    const int lane = tid & 31;
    const int g    = lane >> 2;     // group id (0..7)
    const int q    = lane & 3;      // thread-in-group (0..3)
    float* sPw = sP + wid * 16 * PSTR;

    // ---- Stage Q (big into sKb area, small into sKs area), read A-frags ----
    for (int i = tid; i < BM * 16; i += THREADS) {
        int r = i >> 4, c4 = i & 15;
        float4 vb = ((const float4*)(Qbg + (size_t)(q0 + r) * DHEAD))[c4];
        *((float4*)&sKb[r * KSTR + c4 * 4]) = vb;
        float4 vs = ((const float4*)(Qsg + (size_t)(q0 + r) * DHEAD))[c4];
        *((float4*)&sKs[r * KSTR + c4 * 4]) = vs;
    }
    __syncthreads();

    uint32_t qfb[8][4], qfs[8][4];
    {
        const int r0 = wid * 16 + g;
#pragma unroll
        for (int s = 0; s < 8; s++) {
            int k0 = 8 * s;
            qfb[s][0] = *(const uint32_t*)&sKb[(r0)     * KSTR + k0 + q];
            qfb[s][1] = *(const uint32_t*)&sKb[(r0 + 8) * KSTR + k0 + q];
            qfb[s][2] = *(const uint32_t*)&sKb[(r0)     * KSTR + k0 + 4 + q];
            qfb[s][3] = *(const uint32_t*)&sKb[(r0 + 8) * KSTR + k0 + 4 + q];
            qfs[s][0] = *(const uint32_t*)&sKs[(r0)     * KSTR + k0 + q];
            qfs[s][1] = *(const uint32_t*)&sKs[(r0 + 8) * KSTR + k0 + q];
            qfs[s][2] = *(const uint32_t*)&sKs[(r0)     * KSTR + k0 + 4 + q];
            qfs[s][3] = *(const uint32_t*)&sKs[(r0 + 8) * KSTR + k0 + 4 + q];
        }
    }

    float oacc[8][4];
    float m0 = -1e30f, m1 = -1e30f, l0 = 0.0f, l1 = 0.0f;
#pragma unroll
    for (int n = 0; n < 8; n++)
#pragma unroll
        for (int j = 0; j < 4; j++) oacc[n][j] = 0.0f;

    const int ntiles = qblk + 1;

    for (int kb = 0; kb < ntiles; kb++) {
        const int n0 = kb * BN;

        __syncthreads();   // everyone done reading previous K/V

        // Stage Kb, Ks, V(+tf32 convert)
        for (int i = tid; i < BN * 16; i += THREADS) {
            int r = i >> 4, c4 = i & 15;
            float4 a = ((const float4*)(Kbg + (size_t)(n0 + r) * DHEAD))[c4];
            *((float4*)&sKb[r * KSTR + c4 * 4]) = a;
            float4 b = ((const float4*)(Ksg + (size_t)(n0 + r) * DHEAD))[c4];
            *((float4*)&sKs[r * KSTR + c4 * 4]) = b;
            float4 v = ((const float4*)(Vh + (size_t)(n0 + r) * DHEAD))[c4];
            v.x = __uint_as_float(f2tf32(v.x));
            v.y = __uint_as_float(f2tf32(v.y));
            v.z = __uint_as_float(f2tf32(v.z));
            v.w = __uint_as_float(f2tf32(v.w));
            *((float4*)&sV[r * VSTR + c4 * 4]) = v;
        }
        __syncthreads();

        // ---- S = Q K^T via 3xTF32 ----
        float sacc[8][4];
#pragma unroll
        for (int n = 0; n < 8; n++)
#pragma unroll
            for (int j = 0; j < 4; j++) sacc[n][j] = 0.0f;

#pragma unroll
        for (int s = 0; s < 8; s++) {
            const int k0 = 8 * s;
#pragma unroll
            for (int n = 0; n < 8; n++) {
                const int kr = 8 * n + g;   // key row in tile
                uint32_t kb0 = *(const uint32_t*)&sKb[kr * KSTR + k0 + q];
                uint32_t kb1 = *(const uint32_t*)&sKb[kr * KSTR + k0 + 4 + q];
                uint32_t ks0 = *(const uint32_t*)&sKs[kr * KSTR + k0 + q];
                uint32_t ks1 = *(const uint32_t*)&sKs[kr * KSTR + k0 + 4 + q];
                mma8(sacc[n], qfb[s], kb0, kb1);
                mma8(sacc[n], qfb[s], ks0, ks1);
                mma8(sacc[n], qfs[s], kb0, kb1);
            }
        }

        // ---- Causal mask (only the diagonal tile) ----
        if (kb == ntiles - 1) {
            const int r0 = q0 + wid * 16 + g;
#pragma unroll
            for (int n = 0; n < 8; n++) {
                int c = n0 + 8 * n + 2 * q;
                if (c     > r0)     sacc[n][0] = -1e30f;
                if (c + 1 > r0)     sacc[n][1] = -1e30f;
                if (c     > r0 + 8) sacc[n][2] = -1e30f;
                if (c + 1 > r0 + 8) sacc[n][3] = -1e30f;
            }
        }

        // ---- Online softmax (scores in log2 units) ----
        float mx0 = sacc[0][0], mx1 = sacc[0][2];
#pragma unroll
        for (int n = 0; n < 8; n++) {
            mx0 = fmaxf(mx0, fmaxf(sacc[n][0], sacc[n][1]));
            mx1 = fmaxf(mx1, fmaxf(sacc[n][2], sacc[n][3]));
        }
        mx0 = fmaxf(mx0, __shfl_xor_sync(0xffffffffu, mx0, 1, 4));
        mx0 = fmaxf(mx0, __shfl_xor_sync(0xffffffffu, mx0, 2, 4));
        mx1 = fmaxf(mx1, __shfl_xor_sync(0xffffffffu, mx1, 1, 4));
        mx1 = fmaxf(mx1, __shfl_xor_sync(0xffffffffu, mx1, 2, 4));

        float mn0 = fmaxf(m0, mx0), mn1 = fmaxf(m1, mx1);
        float sc0 = exp2f(m0 - mn0), sc1 = exp2f(m1 - mn1);
        m0 = mn0; m1 = mn1;

        float sum0 = 0.0f, sum1 = 0.0f;
#pragma unroll
        for (int n = 0; n < 8; n++) {
            float p0 = exp2f(sacc[n][0] - m0);
            float p1 = exp2f(sacc[n][1] - m0);
            float p2 = exp2f(sacc[n][2] - m1);
            float p3 = exp2f(sacc[n][3] - m1);
            sum0 += p0 + p1;
            sum1 += p2 + p3;
            float2 w0 = make_float2(__uint_as_float(f2tf32(p0)), __uint_as_float(f2tf32(p1)));
            float2 w1 = make_float2(__uint_as_float(f2tf32(p2)), __uint_as_float(f2tf32(p3)));
            *((float2*)&sPw[(g)     * PSTR + 8 * n + 2 * q]) = w0;
            *((float2*)&sPw[(g + 8) * PSTR + 8 * n + 2 * q]) = w1;
        }
        sum0 += __shfl_xor_sync(0xffffffffu, sum0, 1, 4);
        sum0 += __shfl_xor_sync(0xffffffffu, sum0, 2, 4);
        sum1 += __shfl_xor_sync(0xffffffffu, sum1, 1, 4);
        sum1 += __shfl_xor_sync(0xffffffffu, sum1, 2, 4);
        l0 = l0 * sc0 + sum0;
        l1 = l1 * sc1 + sum1;

#pragma unroll
        for (int n = 0; n < 8; n++) {
            oacc[n][0] *= sc0; oacc[n][1] *= sc0;
            oacc[n][2] *= sc1; oacc[n][3] *= sc1;
        }
        __syncwarp();

        // ---- O += P V ----
#pragma unroll
        for (int s = 0; s < 8; s++) {
            const int k0 = 8 * s;
            uint32_t pf[4];
            pf[0] = *(const uint32_t*)&sPw[(g)     * PSTR + k0 + q];
            pf[1] = *(const uint32_t*)&sPw[(g + 8) * PSTR + k0 + q];
            pf[2] = *(const uint32_t*)&sPw[(g)     * PSTR + k0 + 4 + q];
            pf[3] = *(const uint32_t*)&sPw[(g + 8) * PSTR + k0 + 4 + q];
#pragma unroll
            for (int n = 0; n < 8; n++) {
                uint32_t v0 = *(const uint32_t*)&sV[(k0 + q)     * VSTR + 8 * n + g];
                uint32_t v1 = *(const uint32_t*)&sV[(k0 + 4 + q) * VSTR + 8 * n + g];
                mma8(oacc[n], pf, v0, v1);
            }
        }
        __syncwarp();   // P buffer free for next iteration
    }

    // ---- Epilogue ----
    const int r0 = q0 + wid * 16 + g;
    float inv0 = 1.0f / l0, inv1 = 1.0f / l1;
#pragma unroll
    for (int n = 0; n < 8; n++) {
        *((float2*)&Oh[(size_t)(r0)     * DHEAD + 8 * n + 2 * q]) =
            make_float2(oacc[n][0] * inv0, oacc[n][1] * inv0);
        *((float2*)&Oh[(size_t)(r0 + 8) * DHEAD + 8 * n + 2 * q]) =
            make_float2(oacc[n][2] * inv1, oacc[n][3] * inv1);
    }
}

// ---------------------------------------------------------------------------
extern "C" void kernel_launch(void* const* d_in, const int* in_sizes, int n_in,
                              void* d_out, int out_size) {
    const float* Q = (const float*)d_in[0];
    const float* K = (const float*)d_in[1];
    const float* V = (const float*)d_in[2];
    float*       O = (float*)d_out;

    const int total_pairs = ELEMS / 2;
    rope_split_kernel<<<(total_pairs + 255) / 256, 256>>>(Q, K, total_pairs);

    size_t smem_bytes = (size_t)(2 * BN * KSTR + BN * VSTR + 4 * 16 * PSTR) * sizeof(float);
    cudaFuncSetAttribute(attn_kernel, cudaFuncAttributeMaxDynamicSharedMemorySize,
                         (int)smem_bytes);
    dim3 grid(SEQ / BM, NHEADS);
    attn_kernel<<<grid, THREADS, smem_bytes>>>(V, O);
}

// round 5
// speedup vs baseline: 2.9436x; 1.2877x over previous
#include <cuda_runtime.h>
#include <cuda_bf16.h>
#include <cstdint>

// Problem shape (fixed by dataset)
#define BATCH 2
#define HEADS 16
#define SEQ   2048
#define DHEAD 64
#define NHEADS (BATCH*HEADS)          // 32
#define ELEMS  (NHEADS*SEQ*DHEAD)     // 4194304
#define WORDS  (ELEMS/2)              // bf16x2 packed words

// Tiling
#define BM 64
#define BN 64
#define THREADS 128
#define QSTR 36   // bf16x2-word stride: banks 4g+q, conflict-free fragments
#define VSTR 72   // V smem stride (floats)
#define PSTR 72   // P smem stride (floats)

#define LOG2E 1.4426950408889634f

// bf16 big/small splits of RoPE'd Q (pre-scaled by log2e) and K, packed bf16x2
__device__ uint32_t g_Qb16[WORDS];
__device__ uint32_t g_Qs16[WORDS];
__device__ uint32_t g_Kb16[WORDS];
__device__ uint32_t g_Ks16[WORDS];

__device__ __forceinline__ uint32_t f2tf32(float x) {
    uint32_t r;
    asm("cvt.rna.tf32.f32 %0, %1;" : "=r"(r) : "f"(x));
    return r;
}
__device__ __forceinline__ float ex2f(float x) {
    float y;
    asm("ex2.approx.ftz.f32 %0, %1;" : "=f"(y) : "f"(x));
    return y;
}

// D += A*B, m16n8k16 bf16
__device__ __forceinline__ void mma16(float* c, const uint32_t* a, uint32_t b0, uint32_t b1) {
    asm("mma.sync.aligned.m16n8k16.row.col.f32.bf16.bf16.f32 "
        "{%0,%1,%2,%3}, {%4,%5,%6,%7}, {%8,%9}, {%0,%1,%2,%3};"
        : "+f"(c[0]), "+f"(c[1]), "+f"(c[2]), "+f"(c[3])
        : "r"(a[0]), "r"(a[1]), "r"(a[2]), "r"(a[3]), "r"(b0), "r"(b1));
}
// D += A*B, m16n8k8 tf32
__device__ __forceinline__ void mma8(float* c, const uint32_t* a, uint32_t b0, uint32_t b1) {
    asm("mma.sync.aligned.m16n8k8.row.col.f32.tf32.tf32.f32 "
        "{%0,%1,%2,%3}, {%4,%5,%6,%7}, {%8,%9}, {%0,%1,%2,%3};"
        : "+f"(c[0]), "+f"(c[1]), "+f"(c[2]), "+f"(c[3])
        : "r"(a[0]), "r"(a[1]), "r"(a[2]), "r"(a[3]), "r"(b0), "r"(b1));
}

// ---------------------------------------------------------------------------
// RoPE + log2e fold (Q only) + bf16 big/small split, packed bf16x2 per word.
// idx enumerates (even,odd) dim pairs: t = pair in head dim, s = seq pos.
// ---------------------------------------------------------------------------
__global__ void rope_split_kernel(const float* __restrict__ Q,
                                  const float* __restrict__ K,
                                  int total_pairs) {
    int idx = blockIdx.x * blockDim.x + threadIdx.x;
    if (idx >= total_pairs) return;
    int t = idx & 31;
    int s = (idx >> 5) & (SEQ - 1);

    float div = expf((float)(2 * t) * (-9.210340371976184f / 64.0f));
    float ang = (float)s * div;
    float sn, cs;
    sincosf(ang, &sn, &cs);

    float2 q2 = ((const float2*)Q)[idx];
    float2 k2 = ((const float2*)K)[idx];

    float qx = (q2.x * cs - q2.y * sn) * LOG2E;
    float qy = (q2.x * sn + q2.y * cs) * LOG2E;
    float kx = k2.x * cs - k2.y * sn;
    float ky = k2.x * sn + k2.y * cs;

    __nv_bfloat162 qb = __float22bfloat162_rn(make_float2(qx, qy));
    __nv_bfloat162 kb = __float22bfloat162_rn(make_float2(kx, ky));
    float2 qbf = __bfloat1622float2(qb);
    float2 kbf = __bfloat1622float2(kb);
    __nv_bfloat162 qs = __float22bfloat162_rn(make_float2(qx - qbf.x, qy - qbf.y));
    __nv_bfloat162 ks = __float22bfloat162_rn(make_float2(kx - kbf.x, ky - kbf.y));

    g_Qb16[idx] = *(uint32_t*)&qb;
    g_Qs16[idx] = *(uint32_t*)&qs;
    g_Kb16[idx] = *(uint32_t*)&kb;
    g_Ks16[idx] = *(uint32_t*)&ks;
}

// ---------------------------------------------------------------------------
// Flash attention: bf16x3 tensor-core QK^T, tf32 PV, online softmax (log2).
// 4 warps x 16 query rows. 3 CTAs/SM.
// ---------------------------------------------------------------------------
__global__ __launch_bounds__(THREADS, 3)
void attn_kernel(const float* __restrict__ V, float* __restrict__ O) {
    extern __shared__ float smem[];
    uint32_t* sKb = (uint32_t*)smem;             // [64][QSTR] bf16x2 (Qb then Kb)
    uint32_t* sKs = sKb + BN * QSTR;             // [64][QSTR] bf16x2 (Ks)
    uint32_t* sQs = sKs + BN * QSTR;             // [64][QSTR] bf16x2 (Qs, persistent)
    float*    sV  = (float*)(sQs + BM * QSTR);   // [64][VSTR] tf32 values
    float*    sP  = sV + BN * VSTR;              // 4 x [16][PSTR] per-warp P

    const int qblk = gridDim.x - 1 - blockIdx.x;   // heavy blocks first
    const int bh   = blockIdx.y;
    const int q0   = qblk * BM;

    const uint32_t* Qbg = g_Qb16 + (size_t)bh * SEQ * 32;   // 32 words per row
    const uint32_t* Qsg = g_Qs16 + (size_t)bh * SEQ * 32;
    const uint32_t* Kbg = g_Kb16 + (size_t)bh * SEQ * 32;
    const uint32_t* Ksg = g_Ks16 + (size_t)bh * SEQ * 32;
    const float*    Vh  = V      + (size_t)bh * SEQ * DHEAD;
    float*          Oh  = O      + (size_t)bh * SEQ * DHEAD;

    const int tid  = threadIdx.x;
    const int wid  = tid >> 5;
    const int lane = tid & 31;
    const int g    = lane >> 2;     // 0..7
    const int q    = lane & 3;      // 0..3
    float* sPw = sP + wid * 16 * PSTR;

    // ---- Stage Q: big into sKb (transient), small into sQs (persistent) ----
    for (int i = tid; i < BM * 8; i += THREADS) {
        int r = i >> 3, c4 = i & 7;
        uint4 vb = ((const uint4*)(Qbg + (size_t)(q0 + r) * 32))[c4];
        *((uint4*)&sKb[r * QSTR + c4 * 4]) = vb;
        uint4 vs = ((const uint4*)(Qsg + (size_t)(q0 + r) * 32))[c4];
        *((uint4*)&sQs[r * QSTR + c4 * 4]) = vs;
    }
    __syncthreads();

    // Q-big A-fragments in registers (4 k16 slots x 4 regs)
    uint32_t qfb[4][4];
    {
        const int r0 = wid * 16 + g;
#pragma unroll
        for (int s = 0; s < 4; s++) {
            qfb[s][0] = sKb[(r0)     * QSTR + 8 * s + q];
            qfb[s][1] = sKb[(r0 + 8) * QSTR + 8 * s + q];
            qfb[s][2] = sKb[(r0)     * QSTR + 8 * s + 4 + q];
            qfb[s][3] = sKb[(r0 + 8) * QSTR + 8 * s + 4 + q];
        }
    }

    float oacc[8][4];
    float m0 = -1e30f, m1 = -1e30f, l0 = 0.0f, l1 = 0.0f;
#pragma unroll
    for (int n = 0; n < 8; n++)
#pragma unroll
        for (int j = 0; j < 4; j++) oacc[n][j] = 0.0f;

    const int ntiles = qblk + 1;

    for (int kb = 0; kb < ntiles; kb++) {
        const int n0 = kb * BN;

        __syncthreads();   // all warps done with previous K/V (and Q-big A-frags)

        // Stage Kb, Ks (bf16x2) and V (tf32)
        for (int i = tid; i < BN * 8; i += THREADS) {
            int r = i >> 3, c4 = i & 7;
            uint4 a = ((const uint4*)(Kbg + (size_t)(n0 + r) * 32))[c4];
            *((uint4*)&sKb[r * QSTR + c4 * 4]) = a;
            uint4 b = ((const uint4*)(Ksg + (size_t)(n0 + r) * 32))[c4];
            *((uint4*)&sKs[r * QSTR + c4 * 4]) = b;
        }
        for (int i = tid; i < BN * 16; i += THREADS) {
            int r = i >> 4, c4 = i & 15;
            float4 v = ((const float4*)(Vh + (size_t)(n0 + r) * DHEAD))[c4];
            v.x = __uint_as_float(f2tf32(v.x));
            v.y = __uint_as_float(f2tf32(v.y));
            v.z = __uint_as_float(f2tf32(v.z));
            v.w = __uint_as_float(f2tf32(v.w));
            *((float4*)&sV[r * VSTR + c4 * 4]) = v;
        }
        __syncthreads();

        // ---- S = Q K^T via bf16x3: q1k1 + q1k2 + q2k1 ----
        float sacc[8][4];
#pragma unroll
        for (int n = 0; n < 8; n++)
#pragma unroll
            for (int j = 0; j < 4; j++) sacc[n][j] = 0.0f;

        const int r0 = wid * 16 + g;
#pragma unroll
        for (int s = 0; s < 4; s++) {
            uint32_t qfs[4];
            qfs[0] = sQs[(r0)     * QSTR + 8 * s + q];
            qfs[1] = sQs[(r0 + 8) * QSTR + 8 * s + q];
            qfs[2] = sQs[(r0)     * QSTR + 8 * s + 4 + q];
            qfs[3] = sQs[(r0 + 8) * QSTR + 8 * s + 4 + q];
#pragma unroll
            for (int n = 0; n < 8; n++) {
                const int kr = 8 * n + g;
                uint32_t kb0 = sKb[kr * QSTR + 8 * s + q];
                uint32_t kb1 = sKb[kr * QSTR + 8 * s + 4 + q];
                uint32_t ks0 = sKs[kr * QSTR + 8 * s + q];
                uint32_t ks1 = sKs[kr * QSTR + 8 * s + 4 + q];
                mma16(sacc[n], qfb[s], kb0, kb1);
                mma16(sacc[n], qfb[s], ks0, ks1);
                mma16(sacc[n], qfs,    kb0, kb1);
            }
        }

        // ---- Causal mask (diagonal tile only) ----
        if (kb == ntiles - 1) {
            const int rq = q0 + wid * 16 + g;
#pragma unroll
            for (int n = 0; n < 8; n++) {
                int c = n0 + 8 * n + 2 * q;
                if (c     > rq)     sacc[n][0] = -1e30f;
                if (c + 1 > rq)     sacc[n][1] = -1e30f;
                if (c     > rq + 8) sacc[n][2] = -1e30f;
                if (c + 1 > rq + 8) sacc[n][3] = -1e30f;
            }
        }

        // ---- Online softmax (log2 units) ----
        float mx0 = sacc[0][0], mx1 = sacc[0][2];
#pragma unroll
        for (int n = 0; n < 8; n++) {
            mx0 = fmaxf(mx0, fmaxf(sacc[n][0], sacc[n][1]));
            mx1 = fmaxf(mx1, fmaxf(sacc[n][2], sacc[n][3]));
        }
        mx0 = fmaxf(mx0, __shfl_xor_sync(0xffffffffu, mx0, 1, 4));
        mx0 = fmaxf(mx0, __shfl_xor_sync(0xffffffffu, mx0, 2, 4));
        mx1 = fmaxf(mx1, __shfl_xor_sync(0xffffffffu, mx1, 1, 4));
        mx1 = fmaxf(mx1, __shfl_xor_sync(0xffffffffu, mx1, 2, 4));

        float mn0 = fmaxf(m0, mx0), mn1 = fmaxf(m1, mx1);
        float sc0 = ex2f(m0 - mn0), sc1 = ex2f(m1 - mn1);
        m0 = mn0; m1 = mn1;

        float sum0 = 0.0f, sum1 = 0.0f;
#pragma unroll
        for (int n = 0; n < 8; n++) {
            float p0 = ex2f(sacc[n][0] - m0);
            float p1 = ex2f(sacc[n][1] - m0);
            float p2 = ex2f(sacc[n][2] - m1);
            float p3 = ex2f(sacc[n][3] - m1);
            sum0 += p0 + p1;
            sum1 += p2 + p3;
            float2 w0 = make_float2(__uint_as_float(f2tf32(p0)), __uint_as_float(f2tf32(p1)));
            float2 w1 = make_float2(__uint_as_float(f2tf32(p2)), __uint_as_float(f2tf32(p3)));
            *((float2*)&sPw[(g)     * PSTR + 8 * n + 2 * q]) = w0;
            *((float2*)&sPw[(g + 8) * PSTR + 8 * n + 2 * q]) = w1;
        }
        sum0 += __shfl_xor_sync(0xffffffffu, sum0, 1, 4);
        sum0 += __shfl_xor_sync(0xffffffffu, sum0, 2, 4);
        sum1 += __shfl_xor_sync(0xffffffffu, sum1, 1, 4);
        sum1 += __shfl_xor_sync(0xffffffffu, sum1, 2, 4);
        l0 = l0 * sc0 + sum0;
        l1 = l1 * sc1 + sum1;

#pragma unroll
        for (int n = 0; n < 8; n++) {
            oacc[n][0] *= sc0; oacc[n][1] *= sc0;
            oacc[n][2] *= sc1; oacc[n][3] *= sc1;
        }
        __syncwarp();

        // ---- O += P V (tf32) ----
#pragma unroll
        for (int s = 0; s < 8; s++) {
            const int k0 = 8 * s;
            uint32_t pf[4];
            pf[0] = *(const uint32_t*)&sPw[(g)     * PSTR + k0 + q];
            pf[1] = *(const uint32_t*)&sPw[(g + 8) * PSTR + k0 + q];
            pf[2] = *(const uint32_t*)&sPw[(g)     * PSTR + k0 + 4 + q];
            pf[3] = *(const uint32_t*)&sPw[(g + 8) * PSTR + k0 + 4 + q];
#pragma unroll
            for (int n = 0; n < 8; n++) {
                uint32_t v0 = *(const uint32_t*)&sV[(k0 + q)     * VSTR + 8 * n + g];
                uint32_t v1 = *(const uint32_t*)&sV[(k0 + 4 + q) * VSTR + 8 * n + g];
                mma8(oacc[n], pf, v0, v1);
            }
        }
        __syncwarp();   // P buffer free for next iteration
    }

    // ---- Epilogue ----
    const int rq = q0 + wid * 16 + g;
    float inv0 = 1.0f / l0, inv1 = 1.0f / l1;
#pragma unroll
    for (int n = 0; n < 8; n++) {
        *((float2*)&Oh[(size_t)(rq)     * DHEAD + 8 * n + 2 * q]) =
            make_float2(oacc[n][0] * inv0, oacc[n][1] * inv0);
        *((float2*)&Oh[(size_t)(rq + 8) * DHEAD + 8 * n + 2 * q]) =
            make_float2(oacc[n][2] * inv1, oacc[n][3] * inv1);
    }
}

// ---------------------------------------------------------------------------
extern "C" void kernel_launch(void* const* d_in, const int* in_sizes, int n_in,
                              void* d_out, int out_size) {
    const float* Q = (const float*)d_in[0];
    const float* K = (const float*)d_in[1];
    const float* V = (const float*)d_in[2];
    float*       O = (float*)d_out;

    const int total_pairs = ELEMS / 2;
    rope_split_kernel<<<(total_pairs + 255) / 256, 256>>>(Q, K, total_pairs);

    size_t smem_bytes =
        (size_t)(3 * 64 * QSTR) * sizeof(uint32_t) +               // Kb, Ks, Qs
        (size_t)(BN * VSTR + 4 * 16 * PSTR) * sizeof(float);       // V, P
    cudaFuncSetAttribute(attn_kernel, cudaFuncAttributeMaxDynamicSharedMemorySize,
                         (int)smem_bytes);
    dim3 grid(SEQ / BM, NHEADS);
    attn_kernel<<<grid, THREADS, smem_bytes>>>(V, O);
}

// round 8
// speedup vs baseline: 3.0955x; 1.0516x over previous
#include <cuda_runtime.h>
#include <cuda_bf16.h>
#include <cstdint>

// Problem shape (fixed by dataset)
#define BATCH 2
#define HEADS 16
#define SEQ   2048
#define DHEAD 64
#define NHEADS (BATCH*HEADS)          // 32
#define ELEMS  (NHEADS*SEQ*DHEAD)     // 4194304
#define WORDS  (ELEMS/2)              // bf16x2 packed words

// Tiling
#define BM 128
#define BN 64
#define THREADS 256
#define NWARP 8
#define QSTR 36   // bf16x2-word stride: conflict-free fragments, 16B-aligned rows
#define VSTR 72   // V smem stride (floats)
#define PSTR 72   // P smem stride (floats)

#define LOG2E 1.4426950408889634f

// bf16 big/small splits of RoPE'd Q (pre-scaled by log2e) and K, packed bf16x2
__device__ uint32_t g_Qb16[WORDS];
__device__ uint32_t g_Qs16[WORDS];
__device__ uint32_t g_Kb16[WORDS];
__device__ uint32_t g_Ks16[WORDS];

__device__ __forceinline__ uint32_t f2tf32(float x) {
    uint32_t r;
    asm("cvt.rna.tf32.f32 %0, %1;" : "=r"(r) : "f"(x));
    return r;
}
__device__ __forceinline__ float ex2f(float x) {
    float y;
    asm("ex2.approx.ftz.f32 %0, %1;" : "=f"(y) : "f"(x));
    return y;
}
__device__ __forceinline__ void cpa16(uint32_t dst, const void* src) {
    asm volatile("cp.async.ca.shared.global [%0], [%1], 16;" :: "r"(dst), "l"(src));
}
#define CP_COMMIT() asm volatile("cp.async.commit_group;")
#define CP_WAIT(N)  asm volatile("cp.async.wait_group %0;" :: "n"(N))

// D += A*B, m16n8k16 bf16
__device__ __forceinline__ void mma16(float* c, const uint32_t* a, uint32_t b0, uint32_t b1) {
    asm("mma.sync.aligned.m16n8k16.row.col.f32.bf16.bf16.f32 "
        "{%0,%1,%2,%3}, {%4,%5,%6,%7}, {%8,%9}, {%0,%1,%2,%3};"
        : "+f"(c[0]), "+f"(c[1]), "+f"(c[2]), "+f"(c[3])
        : "r"(a[0]), "r"(a[1]), "r"(a[2]), "r"(a[3]), "r"(b0), "r"(b1));
}
// D += A*B, m16n8k8 tf32
__device__ __forceinline__ void mma8(float* c, const uint32_t* a, uint32_t b0, uint32_t b1) {
    asm("mma.sync.aligned.m16n8k8.row.col.f32.tf32.tf32.f32 "
        "{%0,%1,%2,%3}, {%4,%5,%6,%7}, {%8,%9}, {%0,%1,%2,%3};"
        : "+f"(c[0]), "+f"(c[1]), "+f"(c[2]), "+f"(c[3])
        : "r"(a[0]), "r"(a[1]), "r"(a[2]), "r"(a[3]), "r"(b0), "r"(b1));
}

// ---------------------------------------------------------------------------
// RoPE + log2e fold (Q only) + bf16 big/small split, packed bf16x2 per word.
// ---------------------------------------------------------------------------
__global__ void rope_split_kernel(const float* __restrict__ Q,
                                  const float* __restrict__ K,
                                  int total_pairs) {
    int idx = blockIdx.x * blockDim.x + threadIdx.x;
    if (idx >= total_pairs) return;
    int t = idx & 31;
    int s = (idx >> 5) & (SEQ - 1);

    float div = expf((float)(2 * t) * (-9.210340371976184f / 64.0f));
    float ang = (float)s * div;
    float sn, cs;
    sincosf(ang, &sn, &cs);

    float2 q2 = ((const float2*)Q)[idx];
    float2 k2 = ((const float2*)K)[idx];

    float qx = (q2.x * cs - q2.y * sn) * LOG2E;
    float qy = (q2.x * sn + q2.y * cs) * LOG2E;
    float kx = k2.x * cs - k2.y * sn;
    float ky = k2.x * sn + k2.y * cs;

    __nv_bfloat162 qb = __float22bfloat162_rn(make_float2(qx, qy));
    __nv_bfloat162 kb = __float22bfloat162_rn(make_float2(kx, ky));
    float2 qbf = __bfloat1622float2(qb);
    float2 kbf = __bfloat1622float2(kb);
    __nv_bfloat162 qs = __float22bfloat162_rn(make_float2(qx - qbf.x, qy - qbf.y));
    __nv_bfloat162 ks = __float22bfloat162_rn(make_float2(kx - kbf.x, ky - kbf.y));

    g_Qb16[idx] = *(uint32_t*)&qb;
    g_Qs16[idx] = *(uint32_t*)&qs;
    g_Kb16[idx] = *(uint32_t*)&kb;
    g_Ks16[idx] = *(uint32_t*)&ks;
}

// ---------------------------------------------------------------------------
// Flash attention: bf16x3 QK^T, tf32 PV, online softmax (log2 units).
// BM=128 (8 warps x 16 rows), BN=64. cp.async double-buffered K, prefetched V.
// Uniform cp.async group structure: every iteration commits exactly 2 groups.
// ---------------------------------------------------------------------------
__global__ __launch_bounds__(THREADS, 2)
void attn_kernel(const float* __restrict__ V, float* __restrict__ O) {
    extern __shared__ float smem[];
    // word layout
    uint32_t* sK  = (uint32_t*)smem;            // 2 stages x (Kb 2304 | Ks 2304) words
    uint32_t* sQs = sK + 2 * 4608;              // [128][QSTR] words (persistent)
    float*    sV  = (float*)(sQs + BM * QSTR);  // [64][VSTR] floats
    float*    sP  = sV + BN * VSTR;             // 8 x [16][PSTR] floats

    const int qblk = gridDim.x - 1 - blockIdx.x;   // heavy blocks first
    const int bh   = blockIdx.y;
    const int q0   = qblk * BM;

    const uint32_t* Qbg = g_Qb16 + (size_t)bh * SEQ * 32;   // 32 words per row
    const uint32_t* Qsg = g_Qs16 + (size_t)bh * SEQ * 32;
    const uint32_t* Kbg = g_Kb16 + (size_t)bh * SEQ * 32;
    const uint32_t* Ksg = g_Ks16 + (size_t)bh * SEQ * 32;
    const float*    Vh  = V      + (size_t)bh * SEQ * DHEAD;
    float*          Oh  = O      + (size_t)bh * SEQ * DHEAD;

    const int tid  = threadIdx.x;
    const int wid  = tid >> 5;
    const int lane = tid & 31;
    const int g    = lane >> 2;     // 0..7
    const int q    = lane & 3;      // 0..3
    float* sPw = sP + wid * 16 * PSTR;

    const uint32_t sK_u  = (uint32_t)__cvta_generic_to_shared(sK);
    const uint32_t sQs_u = (uint32_t)__cvta_generic_to_shared(sQs);
    const uint32_t sV_u  = (uint32_t)__cvta_generic_to_shared(sV);

    // ---- Stage Q: big transiently into sK area, small into sQs (persistent) ----
    for (int i = tid; i < BM * 8; i += THREADS) {
        int r = i >> 3, c = i & 7;
        cpa16(sK_u  + (uint32_t)(r * QSTR + c * 4) * 4, Qbg + (size_t)(q0 + r) * 32 + c * 4);
        cpa16(sQs_u + (uint32_t)(r * QSTR + c * 4) * 4, Qsg + (size_t)(q0 + r) * 32 + c * 4);
    }
    CP_COMMIT();
    CP_WAIT(0);
    __syncthreads();

    // Q-big A-fragments in registers (4 k16 slots x 4 regs)
    uint32_t qfb[4][4];
    {
        const int r0 = wid * 16 + g;
#pragma unroll
        for (int s = 0; s < 4; s++) {
            qfb[s][0] = sK[(r0)     * QSTR + 8 * s + q];
            qfb[s][1] = sK[(r0 + 8) * QSTR + 8 * s + q];
            qfb[s][2] = sK[(r0)     * QSTR + 8 * s + 4 + q];
            qfb[s][3] = sK[(r0 + 8) * QSTR + 8 * s + 4 + q];
        }
    }
    __syncthreads();   // fragments read before cp.async K0 overwrites the area

    const int ntiles = 2 * qblk + 2;

    // Prologue: K tile 0 into stage 0
    for (int i = tid; i < BN * 8; i += THREADS) {
        int r = i >> 3, c = i & 7;
        cpa16(sK_u + (uint32_t)(r * QSTR + c * 4) * 4,        Kbg + (size_t)r * 32 + c * 4);
        cpa16(sK_u + (uint32_t)(2304 + r * QSTR + c * 4) * 4, Ksg + (size_t)r * 32 + c * 4);
    }
    CP_COMMIT();

    float oacc[8][4];
    float m0 = -1e30f, m1 = -1e30f, l0 = 0.0f, l1 = 0.0f;
#pragma unroll
    for (int n = 0; n < 8; n++)
#pragma unroll
        for (int j = 0; j < 4; j++) oacc[n][j] = 0.0f;

    for (int kb = 0; kb < ntiles; kb++) {
        const int n0 = kb * BN;

        __syncthreads();   // V readers + next-K-buffer readers done

        // Prefetch V(kb)  — group A of this iteration
        for (int i = tid; i < BN * 16; i += THREADS) {
            int r = i >> 4, c = i & 15;
            cpa16(sV_u + (uint32_t)(r * VSTR + c * 4) * 4, Vh + (size_t)(n0 + r) * DHEAD + c * 4);
        }
        CP_COMMIT();

        // Prefetch K(kb+1) into alternate stage — group B (uniform: on the last
        // iteration the source row is clamped; the fetched data is never read).
        {
            const uint32_t kbase = sK_u + (uint32_t)(((kb + 1) & 1) * 4608) * 4;
            const int n1 = (kb + 1 < ntiles) ? (n0 + BN) : (SEQ - BN);
            for (int i = tid; i < BN * 8; i += THREADS) {
                int r = i >> 3, c = i & 7;
                cpa16(kbase + (uint32_t)(r * QSTR + c * 4) * 4,        Kbg + (size_t)(n1 + r) * 32 + c * 4);
                cpa16(kbase + (uint32_t)(2304 + r * QSTR + c * 4) * 4, Ksg + (size_t)(n1 + r) * 32 + c * 4);
            }
            CP_COMMIT();
        }

        CP_WAIT(2);        // K(kb) landed
        __syncthreads();

        const uint32_t* sKb = sK + (kb & 1) * 4608;
        const uint32_t* sKs = sKb + 2304;

        // ---- S = Q K^T via bf16x3: q1k1 + q1k2 + q2k1 ----
        float sacc[8][4];
#pragma unroll
        for (int n = 0; n < 8; n++)
#pragma unroll
            for (int j = 0; j < 4; j++) sacc[n][j] = 0.0f;

        const int r0 = wid * 16 + g;
#pragma unroll
        for (int s = 0; s < 4; s++) {
            uint32_t qfs[4];
            qfs[0] = sQs[(r0)     * QSTR + 8 * s + q];
            qfs[1] = sQs[(r0 + 8) * QSTR + 8 * s + q];
            qfs[2] = sQs[(r0)     * QSTR + 8 * s + 4 + q];
            qfs[3] = sQs[(r0 + 8) * QSTR + 8 * s + 4 + q];
#pragma unroll
            for (int n = 0; n < 8; n++) {
                const int kr = 8 * n + g;
                uint32_t kb0 = sKb[kr * QSTR + 8 * s + q];
                uint32_t kb1 = sKb[kr * QSTR + 8 * s + 4 + q];
                uint32_t ks0 = sKs[kr * QSTR + 8 * s + q];
                uint32_t ks1 = sKs[kr * QSTR + 8 * s + 4 + q];
                mma16(sacc[n], qfb[s], kb0, kb1);
                mma16(sacc[n], qfb[s], ks0, ks1);
                mma16(sacc[n], qfs,    kb0, kb1);
            }
        }

        // ---- Causal mask (last two key tiles intersect the 128-row diagonal) ----
        if (kb >= ntiles - 2) {
            const int rq = q0 + wid * 16 + g;
#pragma unroll
            for (int n = 0; n < 8; n++) {
                int c = n0 + 8 * n + 2 * q;
                if (c     > rq)     sacc[n][0] = -1e30f;
                if (c + 1 > rq)     sacc[n][1] = -1e30f;
                if (c     > rq + 8) sacc[n][2] = -1e30f;
                if (c + 1 > rq + 8) sacc[n][3] = -1e30f;
            }
        }

        // ---- Online softmax (log2 units) ----
        float mx0 = sacc[0][0], mx1 = sacc[0][2];
#pragma unroll
        for (int n = 0; n < 8; n++) {
            mx0 = fmaxf(mx0, fmaxf(sacc[n][0], sacc[n][1]));
            mx1 = fmaxf(mx1, fmaxf(sacc[n][2], sacc[n][3]));
        }
        mx0 = fmaxf(mx0, __shfl_xor_sync(0xffffffffu, mx0, 1, 4));
        mx0 = fmaxf(mx0, __shfl_xor_sync(0xffffffffu, mx0, 2, 4));
        mx1 = fmaxf(mx1, __shfl_xor_sync(0xffffffffu, mx1, 1, 4));
        mx1 = fmaxf(mx1, __shfl_xor_sync(0xffffffffu, mx1, 2, 4));

        float mn0 = fmaxf(m0, mx0), mn1 = fmaxf(m1, mx1);
        float sc0 = ex2f(m0 - mn0), sc1 = ex2f(m1 - mn1);
        m0 = mn0; m1 = mn1;

        float sum0 = 0.0f, sum1 = 0.0f;
#pragma unroll
        for (int n = 0; n < 8; n++) {
            float p0 = ex2f(sacc[n][0] - m0);
            float p1 = ex2f(sacc[n][1] - m0);
            float p2 = ex2f(sacc[n][2] - m1);
            float p3 = ex2f(sacc[n][3] - m1);
            sum0 += p0 + p1;
            sum1 += p2 + p3;
            float2 w0 = make_float2(__uint_as_float(f2tf32(p0)), __uint_as_float(f2tf32(p1)));
            float2 w1 = make_float2(__uint_as_float(f2tf32(p2)), __uint_as_float(f2tf32(p3)));
            *((float2*)&sPw[(g)     * PSTR + 8 * n + 2 * q]) = w0;
            *((float2*)&sPw[(g + 8) * PSTR + 8 * n + 2 * q]) = w1;
        }
        sum0 += __shfl_xor_sync(0xffffffffu, sum0, 1, 4);
        sum0 += __shfl_xor_sync(0xffffffffu, sum0, 2, 4);
        sum1 += __shfl_xor_sync(0xffffffffu, sum1, 1, 4);
        sum1 += __shfl_xor_sync(0xffffffffu, sum1, 2, 4);
        l0 = l0 * sc0 + sum0;
        l1 = l1 * sc1 + sum1;

#pragma unroll
        for (int n = 0; n < 8; n++) {
            oacc[n][0] *= sc0; oacc[n][1] *= sc0;
            oacc[n][2] *= sc1; oacc[n][3] *= sc1;
        }
        __syncwarp();

        CP_WAIT(1);        // V(kb) landed (K(kb+1) may still be in flight)
        __syncthreads();

        // ---- O += P V (tf32; V raw fp32 operand is HW-truncated to tf32) ----
#pragma unroll
        for (int s = 0; s < 8; s++) {
            const int k0 = 8 * s;
            uint32_t pf[4];
            pf[0] = *(const uint32_t*)&sPw[(g)     * PSTR + k0 + q];
            pf[1] = *(const uint32_t*)&sPw[(g + 8) * PSTR + k0 + q];
            pf[2] = *(const uint32_t*)&sPw[(g)     * PSTR + k0 + 4 + q];
            pf[3] = *(const uint32_t*)&sPw[(g + 8) * PSTR + k0 + 4 + q];
#pragma unroll
            for (int n = 0; n < 8; n++) {
                uint32_t v0 = *(const uint32_t*)&sV[(k0 + q)     * VSTR + 8 * n + g];
                uint32_t v1 = *(const uint32_t*)&sV[(k0 + 4 + q) * VSTR + 8 * n + g];
                mma8(oacc[n], pf, v0, v1);
            }
        }
    }

    // ---- Epilogue ----
    const int rq = q0 + wid * 16 + g;
    float inv0 = 1.0f / l0, inv1 = 1.0f / l1;
#pragma unroll
    for (int n = 0; n < 8; n++) {
        *((float2*)&Oh[(size_t)(rq)     * DHEAD + 8 * n + 2 * q]) =
            make_float2(oacc[n][0] * inv0, oacc[n][1] * inv0);
        *((float2*)&Oh[(size_t)(rq + 8) * DHEAD + 8 * n + 2 * q]) =
            make_float2(oacc[n][2] * inv1, oacc[n][3] * inv1);
    }
}

// ---------------------------------------------------------------------------
extern "C" void kernel_launch(void* const* d_in, const int* in_sizes, int n_in,
                              void* d_out, int out_size) {
    const float* Q = (const float*)d_in[0];
    const float* K = (const float*)d_in[1];
    const float* V = (const float*)d_in[2];
    float*       O = (float*)d_out;

    const int total_pairs = ELEMS / 2;
    rope_split_kernel<<<(total_pairs + 255) / 256, 256>>>(Q, K, total_pairs);

    size_t smem_bytes =
        (size_t)(2 * 4608 + BM * QSTR) * sizeof(uint32_t) +        // K stages + Qs
        (size_t)(BN * VSTR + NWARP * 16 * PSTR) * sizeof(float);   // V + P
    cudaFuncSetAttribute(attn_kernel, cudaFuncAttributeMaxDynamicSharedMemorySize,
                         (int)smem_bytes);
    dim3 grid(SEQ / BM, NHEADS);
    attn_kernel<<<grid, THREADS, smem_bytes>>>(V, O);
}

// round 9
// speedup vs baseline: 3.2088x; 1.0366x over previous
#include <cuda_runtime.h>
#include <cuda_bf16.h>
#include <cstdint>

// Problem shape (fixed by dataset)
#define BATCH 2
#define HEADS 16
#define SEQ   2048
#define DHEAD 64
#define NHEADS (BATCH*HEADS)          // 32
#define ELEMS  (NHEADS*SEQ*DHEAD)     // 4194304
#define WORDS  (ELEMS/2)              // bf16x2 packed words

// Tiling
#define BM 128
#define BN 64
#define THREADS 256
#define NWARP 8
#define QSTR 36   // bf16x2-word stride
#define VSTR 72   // V smem stride (floats)
#define PSTR 72   // P smem stride (floats)

#define LOG2E 1.4426950408889634f

// bf16 big/small splits of RoPE'd Q (pre-scaled by log2e) and K, packed bf16x2
__device__ uint32_t g_Qb16[WORDS];
__device__ uint32_t g_Qs16[WORDS];
__device__ uint32_t g_Kb16[WORDS];
__device__ uint32_t g_Ks16[WORDS];
// V pre-rounded to tf32 (rna) — keeps PV accumulation unbiased
__device__ float    g_Vt[ELEMS];

__device__ __forceinline__ uint32_t f2tf32(float x) {
    uint32_t r;
    asm("cvt.rna.tf32.f32 %0, %1;" : "=r"(r) : "f"(x));
    return r;
}
__device__ __forceinline__ float ex2f(float x) {
    float y;
    asm("ex2.approx.ftz.f32 %0, %1;" : "=f"(y) : "f"(x));
    return y;
}
__device__ __forceinline__ void cpa16(uint32_t dst, const void* src) {
    asm volatile("cp.async.ca.shared.global [%0], [%1], 16;" :: "r"(dst), "l"(src));
}
#define CP_COMMIT() asm volatile("cp.async.commit_group;")
#define CP_WAIT(N)  asm volatile("cp.async.wait_group %0;" :: "n"(N))

__device__ __forceinline__ void ldsm4(uint32_t& a, uint32_t& b, uint32_t& c, uint32_t& d,
                                      uint32_t addr) {
    asm volatile("ldmatrix.sync.aligned.m8n8.x4.shared.b16 {%0,%1,%2,%3}, [%4];"
        : "=r"(a), "=r"(b), "=r"(c), "=r"(d) : "r"(addr));
}

// D += A*B, m16n8k16 bf16
__device__ __forceinline__ void mma16(float* c, const uint32_t* a, uint32_t b0, uint32_t b1) {
    asm("mma.sync.aligned.m16n8k16.row.col.f32.bf16.bf16.f32 "
        "{%0,%1,%2,%3}, {%4,%5,%6,%7}, {%8,%9}, {%0,%1,%2,%3};"
        : "+f"(c[0]), "+f"(c[1]), "+f"(c[2]), "+f"(c[3])
        : "r"(a[0]), "r"(a[1]), "r"(a[2]), "r"(a[3]), "r"(b0), "r"(b1));
}
// D += A*B, m16n8k8 tf32
__device__ __forceinline__ void mma8(float* c, const uint32_t* a, uint32_t b0, uint32_t b1) {
    asm("mma.sync.aligned.m16n8k8.row.col.f32.tf32.tf32.f32 "
        "{%0,%1,%2,%3}, {%4,%5,%6,%7}, {%8,%9}, {%0,%1,%2,%3};"
        : "+f"(c[0]), "+f"(c[1]), "+f"(c[2]), "+f"(c[3])
        : "r"(a[0]), "r"(a[1]), "r"(a[2]), "r"(a[3]), "r"(b0), "r"(b1));
}

// ---------------------------------------------------------------------------
// RoPE + log2e fold (Q) + bf16 big/small split, + V -> tf32(rna) pre-round.
// ---------------------------------------------------------------------------
__global__ void rope_split_kernel(const float* __restrict__ Q,
                                  const float* __restrict__ K,
                                  const float* __restrict__ V,
                                  int total_pairs) {
    int idx = blockIdx.x * blockDim.x + threadIdx.x;
    if (idx >= total_pairs) return;
    int t = idx & 31;
    int s = (idx >> 5) & (SEQ - 1);

    float div = expf((float)(2 * t) * (-9.210340371976184f / 64.0f));
    float ang = (float)s * div;
    float sn, cs;
    sincosf(ang, &sn, &cs);

    float2 q2 = ((const float2*)Q)[idx];
    float2 k2 = ((const float2*)K)[idx];
    float2 v2 = ((const float2*)V)[idx];

    float qx = (q2.x * cs - q2.y * sn) * LOG2E;
    float qy = (q2.x * sn + q2.y * cs) * LOG2E;
    float kx = k2.x * cs - k2.y * sn;
    float ky = k2.x * sn + k2.y * cs;

    __nv_bfloat162 qb = __float22bfloat162_rn(make_float2(qx, qy));
    __nv_bfloat162 kb = __float22bfloat162_rn(make_float2(kx, ky));
    float2 qbf = __bfloat1622float2(qb);
    float2 kbf = __bfloat1622float2(kb);
    __nv_bfloat162 qs = __float22bfloat162_rn(make_float2(qx - qbf.x, qy - qbf.y));
    __nv_bfloat162 ks = __float22bfloat162_rn(make_float2(kx - kbf.x, ky - kbf.y));

    g_Qb16[idx] = *(uint32_t*)&qb;
    g_Qs16[idx] = *(uint32_t*)&qs;
    g_Kb16[idx] = *(uint32_t*)&kb;
    g_Ks16[idx] = *(uint32_t*)&ks;
    ((float2*)g_Vt)[idx] = make_float2(__uint_as_float(f2tf32(v2.x)),
                                       __uint_as_float(f2tf32(v2.y)));
}

// ---------------------------------------------------------------------------
// Flash attention: bf16x3 QK^T (ldmatrix operands), tf32 PV, log2 softmax.
// BM=128 (8 warps x 16 rows), BN=64. cp.async double-buffered K, prefetched V.
// ---------------------------------------------------------------------------
__global__ __launch_bounds__(THREADS, 2)
void attn_kernel(float* __restrict__ O) {
    extern __shared__ float smem[];
    uint32_t* sK  = (uint32_t*)smem;            // 2 stages x (Kb 2304 | Ks 2304) words
    uint32_t* sQs = sK + 2 * 4608;              // [128][QSTR] words (persistent)
    float*    sV  = (float*)(sQs + BM * QSTR);  // [64][VSTR] floats
    float*    sP  = sV + BN * VSTR;             // 8 x [16][PSTR] floats

    const int qblk = gridDim.x - 1 - blockIdx.x;   // heavy blocks first
    const int bh   = blockIdx.y;
    const int q0   = qblk * BM;

    const uint32_t* Qbg = g_Qb16 + (size_t)bh * SEQ * 32;
    const uint32_t* Qsg = g_Qs16 + (size_t)bh * SEQ * 32;
    const uint32_t* Kbg = g_Kb16 + (size_t)bh * SEQ * 32;
    const uint32_t* Ksg = g_Ks16 + (size_t)bh * SEQ * 32;
    const float*    Vtg = g_Vt   + (size_t)bh * SEQ * DHEAD;
    float*          Oh  = O      + (size_t)bh * SEQ * DHEAD;

    const int tid  = threadIdx.x;
    const int wid  = tid >> 5;
    const int lane = tid & 31;
    const int g    = lane >> 2;     // 0..7
    const int q    = lane & 3;      // 0..3
    const int l8   = lane & 7;      // ldmatrix row within 8x8 tile
    const int sel  = lane >> 3;     // ldmatrix tile selector 0..3
    float* sPw = sP + wid * 16 * PSTR;

    const uint32_t sK_u  = (uint32_t)__cvta_generic_to_shared(sK);
    const uint32_t sQs_u = (uint32_t)__cvta_generic_to_shared(sQs);
    const uint32_t sV_u  = (uint32_t)__cvta_generic_to_shared(sV);

    // ldmatrix per-lane byte offsets:
    // Q A-fragments (a0: rows r..r+7 k-lo, a1: rows+8 k-lo, a2: k-hi, a3: +8 k-hi)
    const uint32_t qoff = (uint32_t)(((wid * 16 + ((sel & 1) << 3) + l8) * QSTR
                                      + ((sel >> 1) << 2)) * 4);
    // K B-fragments (R0=Kb k-lo, R1=Kb k-hi, R2=Ks k-lo, R3=Ks k-hi)
    const uint32_t boff = (uint32_t)(((sel >> 1) ? 2304 * 4 : 0)
                                     + (l8 * QSTR + ((sel & 1) << 2)) * 4);

    // ---- Stage Q: big transiently into sK area, small into sQs (persistent) ----
    for (int i = tid; i < BM * 8; i += THREADS) {
        int r = i >> 3, c = i & 7;
        cpa16(sK_u  + (uint32_t)(r * QSTR + c * 4) * 4, Qbg + (size_t)(q0 + r) * 32 + c * 4);
        cpa16(sQs_u + (uint32_t)(r * QSTR + c * 4) * 4, Qsg + (size_t)(q0 + r) * 32 + c * 4);
    }
    CP_COMMIT();
    CP_WAIT(0);
    __syncthreads();

    // Q-big A-fragments in registers (4 k16 slots x 4 regs), via ldmatrix
    uint32_t qfb[4][4];
#pragma unroll
    for (int s = 0; s < 4; s++)
        ldsm4(qfb[s][0], qfb[s][1], qfb[s][2], qfb[s][3], sK_u + qoff + s * 32);
    __syncthreads();   // fragments read before cp.async K0 overwrites the area

    const int ntiles = 2 * qblk + 2;

    // Prologue: K tile 0 into stage 0
    for (int i = tid; i < BN * 8; i += THREADS) {
        int r = i >> 3, c = i & 7;
        cpa16(sK_u + (uint32_t)(r * QSTR + c * 4) * 4,        Kbg + (size_t)r * 32 + c * 4);
        cpa16(sK_u + (uint32_t)(2304 + r * QSTR + c * 4) * 4, Ksg + (size_t)r * 32 + c * 4);
    }
    CP_COMMIT();

    float oacc[8][4];
    float m0 = -1e30f, m1 = -1e30f, l0 = 0.0f, l1 = 0.0f;
#pragma unroll
    for (int n = 0; n < 8; n++)
#pragma unroll
        for (int j = 0; j < 4; j++) oacc[n][j] = 0.0f;

    for (int kb = 0; kb < ntiles; kb++) {
        const int n0 = kb * BN;

        __syncthreads();   // V readers + next-K-buffer readers done

        // Prefetch V(kb)
        for (int i = tid; i < BN * 16; i += THREADS) {
            int r = i >> 4, c = i & 15;
            cpa16(sV_u + (uint32_t)(r * VSTR + c * 4) * 4, Vtg + (size_t)(n0 + r) * DHEAD + c * 4);
        }
        CP_COMMIT();

        // Prefetch K(kb+1) into alternate stage (uniform; clamped on last iter)
        {
            const uint32_t kbase = sK_u + (uint32_t)(((kb + 1) & 1) * 4608) * 4;
            const int n1 = (kb + 1 < ntiles) ? (n0 + BN) : (SEQ - BN);
            for (int i = tid; i < BN * 8; i += THREADS) {
                int r = i >> 3, c = i & 7;
                cpa16(kbase + (uint32_t)(r * QSTR + c * 4) * 4,        Kbg + (size_t)(n1 + r) * 32 + c * 4);
                cpa16(kbase + (uint32_t)(2304 + r * QSTR + c * 4) * 4, Ksg + (size_t)(n1 + r) * 32 + c * 4);
            }
            CP_COMMIT();
        }

        CP_WAIT(2);        // K(kb) landed
        __syncthreads();

        const uint32_t kstage = sK_u + (uint32_t)((kb & 1) * 4608) * 4;

        // ---- S = Q K^T via bf16x3: q1k1 + q1k2 + q2k1 (ldmatrix operands) ----
        float sacc[8][4];
#pragma unroll
        for (int n = 0; n < 8; n++)
#pragma unroll
            for (int j = 0; j < 4; j++) sacc[n][j] = 0.0f;

#pragma unroll
        for (int s = 0; s < 4; s++) {
            uint32_t qfs[4];
            ldsm4(qfs[0], qfs[1], qfs[2], qfs[3], sQs_u + qoff + s * 32);
#pragma unroll
            for (int n = 0; n < 8; n++) {
                uint32_t b0, b1, b2, b3;   // Kb-lo, Kb-hi, Ks-lo, Ks-hi
                ldsm4(b0, b1, b2, b3, kstage + boff + (uint32_t)(n * (8 * QSTR * 4) + s * 32));
                mma16(sacc[n], qfb[s], b0, b1);
                mma16(sacc[n], qfb[s], b2, b3);
                mma16(sacc[n], qfs,    b0, b1);
            }
        }

        // ---- Causal mask (last two key tiles intersect the 128-row diagonal) ----
        if (kb >= ntiles - 2) {
            const int rq = q0 + wid * 16 + g;
#pragma unroll
            for (int n = 0; n < 8; n++) {
                int c = n0 + 8 * n + 2 * q;
                if (c     > rq)     sacc[n][0] = -1e30f;
                if (c + 1 > rq)     sacc[n][1] = -1e30f;
                if (c     > rq + 8) sacc[n][2] = -1e30f;
                if (c + 1 > rq + 8) sacc[n][3] = -1e30f;
            }
        }

        // ---- Online softmax (log2 units) ----
        float mx0 = sacc[0][0], mx1 = sacc[0][2];
#pragma unroll
        for (int n = 0; n < 8; n++) {
            mx0 = fmaxf(mx0, fmaxf(sacc[n][0], sacc[n][1]));
            mx1 = fmaxf(mx1, fmaxf(sacc[n][2], sacc[n][3]));
        }
        mx0 = fmaxf(mx0, __shfl_xor_sync(0xffffffffu, mx0, 1, 4));
        mx0 = fmaxf(mx0, __shfl_xor_sync(0xffffffffu, mx0, 2, 4));
        mx1 = fmaxf(mx1, __shfl_xor_sync(0xffffffffu, mx1, 1, 4));
        mx1 = fmaxf(mx1, __shfl_xor_sync(0xffffffffu, mx1, 2, 4));

        float mn0 = fmaxf(m0, mx0), mn1 = fmaxf(m1, mx1);
        float sc0 = ex2f(m0 - mn0), sc1 = ex2f(m1 - mn1);
        m0 = mn0; m1 = mn1;

        float sum0 = 0.0f, sum1 = 0.0f;
#pragma unroll
        for (int n = 0; n < 8; n++) {
            float p0 = ex2f(sacc[n][0] - m0);
            float p1 = ex2f(sacc[n][1] - m0);
            float p2 = ex2f(sacc[n][2] - m1);
            float p3 = ex2f(sacc[n][3] - m1);
            sum0 += p0 + p1;
            sum1 += p2 + p3;
            float2 w0 = make_float2(__uint_as_float(f2tf32(p0)), __uint_as_float(f2tf32(p1)));
            float2 w1 = make_float2(__uint_as_float(f2tf32(p2)), __uint_as_float(f2tf32(p3)));
            *((float2*)&sPw[(g)     * PSTR + 8 * n + 2 * q]) = w0;
            *((float2*)&sPw[(g + 8) * PSTR + 8 * n + 2 * q]) = w1;
        }
        sum0 += __shfl_xor_sync(0xffffffffu, sum0, 1, 4);
        sum0 += __shfl_xor_sync(0xffffffffu, sum0, 2, 4);
        sum1 += __shfl_xor_sync(0xffffffffu, sum1, 1, 4);
        sum1 += __shfl_xor_sync(0xffffffffu, sum1, 2, 4);
        l0 = l0 * sc0 + sum0;
        l1 = l1 * sc1 + sum1;

#pragma unroll
        for (int n = 0; n < 8; n++) {
            oacc[n][0] *= sc0; oacc[n][1] *= sc0;
            oacc[n][2] *= sc1; oacc[n][3] *= sc1;
        }
        __syncwarp();

        CP_WAIT(1);        // V(kb) landed (K(kb+1) may still be in flight)
        __syncthreads();

        // ---- O += P V (tf32; V pre-rounded rna in gmem scratch) ----
#pragma unroll
        for (int s = 0; s < 8; s++) {
            const int k0 = 8 * s;
            uint32_t pf[4];
            pf[0] = *(const uint32_t*)&sPw[(g)     * PSTR + k0 + q];
            pf[1] = *(const uint32_t*)&sPw[(g + 8) * PSTR + k0 + q];
            pf[2] = *(const uint32_t*)&sPw[(g)     * PSTR + k0 + 4 + q];
            pf[3] = *(const uint32_t*)&sPw[(g + 8) * PSTR + k0 + 4 + q];
#pragma unroll
            for (int n = 0; n < 8; n++) {
                uint32_t v0 = *(const uint32_t*)&sV[(k0 + q)     * VSTR + 8 * n + g];
                uint32_t v1 = *(const uint32_t*)&sV[(k0 + 4 + q) * VSTR + 8 * n + g];
                mma8(oacc[n], pf, v0, v1);
            }
        }
    }

    // ---- Epilogue ----
    const int rq = q0 + wid * 16 + g;
    float inv0 = 1.0f / l0, inv1 = 1.0f / l1;
#pragma unroll
    for (int n = 0; n < 8; n++) {
        *((float2*)&Oh[(size_t)(rq)     * DHEAD + 8 * n + 2 * q]) =
            make_float2(oacc[n][0] * inv0, oacc[n][1] * inv0);
        *((float2*)&Oh[(size_t)(rq + 8) * DHEAD + 8 * n + 2 * q]) =
            make_float2(oacc[n][2] * inv1, oacc[n][3] * inv1);
    }
}

// ---------------------------------------------------------------------------
extern "C" void kernel_launch(void* const* d_in, const int* in_sizes, int n_in,
                              void* d_out, int out_size) {
    const float* Q = (const float*)d_in[0];
    const float* K = (const float*)d_in[1];
    const float* V = (const float*)d_in[2];
    float*       O = (float*)d_out;

    const int total_pairs = ELEMS / 2;
    rope_split_kernel<<<(total_pairs + 255) / 256, 256>>>(Q, K, V, total_pairs);

    size_t smem_bytes =
        (size_t)(2 * 4608 + BM * QSTR) * sizeof(uint32_t) +        // K stages + Qs
        (size_t)(BN * VSTR + NWARP * 16 * PSTR) * sizeof(float);   // V + P
    cudaFuncSetAttribute(attn_kernel, cudaFuncAttributeMaxDynamicSharedMemorySize,
                         (int)smem_bytes);
    dim3 grid(SEQ / BM, NHEADS);
    attn_kernel<<<grid, THREADS, smem_bytes>>>(O);
}

// round 10
// speedup vs baseline: 3.2411x; 1.0101x over previous
#include <cuda_runtime.h>
#include <cuda_bf16.h>
#include <cstdint>

// Problem shape (fixed by dataset)
#define BATCH 2
#define HEADS 16
#define SEQ   2048
#define DHEAD 64
#define NHEADS (BATCH*HEADS)          // 32
#define ELEMS  (NHEADS*SEQ*DHEAD)     // 4194304
#define WORDS  (ELEMS/2)              // bf16x2 packed words

// Tiling
#define BM 128
#define BN 64
#define THREADS 256
#define NWARP 8
#define QSTR 36   // bf16x2-word stride
#define VSTR 72   // V smem stride (floats)
#define PSTR 72   // P smem stride (floats)

#define LOG2E 1.4426950408889634f

// bf16 big/small splits of RoPE'd Q (pre-scaled by log2e) and K, packed bf16x2
__device__ uint32_t g_Qb16[WORDS];
__device__ uint32_t g_Qs16[WORDS];
__device__ uint32_t g_Kb16[WORDS];
__device__ uint32_t g_Ks16[WORDS];
// V pre-rounded to tf32 (rna) — keeps PV accumulation unbiased
__device__ float    g_Vt[ELEMS];

__device__ __forceinline__ uint32_t f2tf32(float x) {
    uint32_t r;
    asm("cvt.rna.tf32.f32 %0, %1;" : "=r"(r) : "f"(x));
    return r;
}
__device__ __forceinline__ float ex2f(float x) {
    float y;
    asm("ex2.approx.ftz.f32 %0, %1;" : "=f"(y) : "f"(x));
    return y;
}
__device__ __forceinline__ void cpa16(uint32_t dst, const void* src) {
    asm volatile("cp.async.ca.shared.global [%0], [%1], 16;" :: "r"(dst), "l"(src));
}
#define CP_COMMIT() asm volatile("cp.async.commit_group;")
#define CP_WAIT(N)  asm volatile("cp.async.wait_group %0;" :: "n"(N))

__device__ __forceinline__ void ldsm4(uint32_t& a, uint32_t& b, uint32_t& c, uint32_t& d,
                                      uint32_t addr) {
    asm volatile("ldmatrix.sync.aligned.m8n8.x4.shared.b16 {%0,%1,%2,%3}, [%4];"
        : "=r"(a), "=r"(b), "=r"(c), "=r"(d) : "r"(addr));
}

// D += A*B, m16n8k16 bf16
__device__ __forceinline__ void mma16(float* c, const uint32_t* a, uint32_t b0, uint32_t b1) {
    asm("mma.sync.aligned.m16n8k16.row.col.f32.bf16.bf16.f32 "
        "{%0,%1,%2,%3}, {%4,%5,%6,%7}, {%8,%9}, {%0,%1,%2,%3};"
        : "+f"(c[0]), "+f"(c[1]), "+f"(c[2]), "+f"(c[3])
        : "r"(a[0]), "r"(a[1]), "r"(a[2]), "r"(a[3]), "r"(b0), "r"(b1));
}
// D += A*B, m16n8k8 tf32
__device__ __forceinline__ void mma8(float* c, const uint32_t* a, uint32_t b0, uint32_t b1) {
    asm("mma.sync.aligned.m16n8k8.row.col.f32.tf32.tf32.f32 "
        "{%0,%1,%2,%3}, {%4,%5,%6,%7}, {%8,%9}, {%0,%1,%2,%3};"
        : "+f"(c[0]), "+f"(c[1]), "+f"(c[2]), "+f"(c[3])
        : "r"(a[0]), "r"(a[1]), "r"(a[2]), "r"(a[3]), "r"(b0), "r"(b1));
}

// ---------------------------------------------------------------------------
// RoPE + log2e fold (Q) + bf16 big/small split, + V -> tf32(rna) pre-round.
// ---------------------------------------------------------------------------
__global__ void rope_split_kernel(const float* __restrict__ Q,
                                  const float* __restrict__ K,
                                  const float* __restrict__ V,
                                  int total_pairs) {
    int idx = blockIdx.x * blockDim.x + threadIdx.x;
    if (idx >= total_pairs) return;
    int t = idx & 31;
    int s = (idx >> 5) & (SEQ - 1);

    float div = expf((float)(2 * t) * (-9.210340371976184f / 64.0f));
    float ang = (float)s * div;
    float sn, cs;
    sincosf(ang, &sn, &cs);

    float2 q2 = ((const float2*)Q)[idx];
    float2 k2 = ((const float2*)K)[idx];
    float2 v2 = ((const float2*)V)[idx];

    float qx = (q2.x * cs - q2.y * sn) * LOG2E;
    float qy = (q2.x * sn + q2.y * cs) * LOG2E;
    float kx = k2.x * cs - k2.y * sn;
    float ky = k2.x * sn + k2.y * cs;

    __nv_bfloat162 qb = __float22bfloat162_rn(make_float2(qx, qy));
    __nv_bfloat162 kb = __float22bfloat162_rn(make_float2(kx, ky));
    float2 qbf = __bfloat1622float2(qb);
    float2 kbf = __bfloat1622float2(kb);
    __nv_bfloat162 qs = __float22bfloat162_rn(make_float2(qx - qbf.x, qy - qbf.y));
    __nv_bfloat162 ks = __float22bfloat162_rn(make_float2(kx - kbf.x, ky - kbf.y));

    g_Qb16[idx] = *(uint32_t*)&qb;
    g_Qs16[idx] = *(uint32_t*)&qs;
    g_Kb16[idx] = *(uint32_t*)&kb;
    g_Ks16[idx] = *(uint32_t*)&ks;
    ((float2*)g_Vt)[idx] = make_float2(__uint_as_float(f2tf32(v2.x)),
                                       __uint_as_float(f2tf32(v2.y)));
}

// ---------------------------------------------------------------------------
// Flash attention: bf16x3 QK^T (ldmatrix operands), tf32 PV, log2 softmax.
// BM=128 (8 warps x 16 rows), BN=64. cp.async double-buffered K, prefetched V.
// ---------------------------------------------------------------------------
__global__ __launch_bounds__(THREADS, 2)
void attn_kernel(float* __restrict__ O) {
    extern __shared__ float smem[];
    uint32_t* sK  = (uint32_t*)smem;            // 2 stages x (Kb 2304 | Ks 2304) words
    uint32_t* sQs = sK + 2 * 4608;              // [128][QSTR] words (persistent)
    float*    sV  = (float*)(sQs + BM * QSTR);  // [64][VSTR] floats
    float*    sP  = sV + BN * VSTR;             // 8 x [16][PSTR] floats

    const int qblk = gridDim.x - 1 - blockIdx.x;   // heavy blocks first
    const int bh   = blockIdx.y;
    const int q0   = qblk * BM;

    const uint32_t* Qbg = g_Qb16 + (size_t)bh * SEQ * 32;
    const uint32_t* Qsg = g_Qs16 + (size_t)bh * SEQ * 32;
    const uint32_t* Kbg = g_Kb16 + (size_t)bh * SEQ * 32;
    const uint32_t* Ksg = g_Ks16 + (size_t)bh * SEQ * 32;
    const float*    Vtg = g_Vt   + (size_t)bh * SEQ * DHEAD;
    float*          Oh  = O      + (size_t)bh * SEQ * DHEAD;

    const int tid  = threadIdx.x;
    const int wid  = tid >> 5;
    const int lane = tid & 31;
    const int g    = lane >> 2;     // 0..7
    const int q    = lane & 3;      // 0..3
    const int l8   = lane & 7;      // ldmatrix row within 8x8 tile
    const int sel  = lane >> 3;     // ldmatrix tile selector 0..3
    float* sPw = sP + wid * 16 * PSTR;

    const uint32_t sK_u  = (uint32_t)__cvta_generic_to_shared(sK);
    const uint32_t sQs_u = (uint32_t)__cvta_generic_to_shared(sQs);
    const uint32_t sV_u  = (uint32_t)__cvta_generic_to_shared(sV);

    // ldmatrix per-lane byte offsets:
    // Q A-fragments (a0: rows r..r+7 k-lo, a1: rows+8 k-lo, a2: k-hi, a3: +8 k-hi)
    const uint32_t qoff = (uint32_t)(((wid * 16 + ((sel & 1) << 3) + l8) * QSTR
                                      + ((sel >> 1) << 2)) * 4);
    // K B-fragments (R0=Kb k-lo, R1=Kb k-hi, R2=Ks k-lo, R3=Ks k-hi)
    const uint32_t boff = (uint32_t)(((sel >> 1) ? 2304 * 4 : 0)
                                     + (l8 * QSTR + ((sel & 1) << 2)) * 4);

    // ---- Stage Q: big transiently into sK area, small into sQs (persistent) ----
    for (int i = tid; i < BM * 8; i += THREADS) {
        int r = i >> 3, c = i & 7;
        cpa16(sK_u  + (uint32_t)(r * QSTR + c * 4) * 4, Qbg + (size_t)(q0 + r) * 32 + c * 4);
        cpa16(sQs_u + (uint32_t)(r * QSTR + c * 4) * 4, Qsg + (size_t)(q0 + r) * 32 + c * 4);
    }
    CP_COMMIT();
    CP_WAIT(0);
    __syncthreads();

    // Q-big A-fragments in registers (4 k16 slots x 4 regs), via ldmatrix
    uint32_t qfb[4][4];
#pragma unroll
    for (int s = 0; s < 4; s++)
        ldsm4(qfb[s][0], qfb[s][1], qfb[s][2], qfb[s][3], sK_u + qoff + s * 32);
    __syncthreads();   // fragments read before cp.async K0 overwrites the area

    const int ntiles = 2 * qblk + 2;

    // Prologue: K tile 0 into stage 0
    for (int i = tid; i < BN * 8; i += THREADS) {
        int r = i >> 3, c = i & 7;
        cpa16(sK_u + (uint32_t)(r * QSTR + c * 4) * 4,        Kbg + (size_t)r * 32 + c * 4);
        cpa16(sK_u + (uint32_t)(2304 + r * QSTR + c * 4) * 4, Ksg + (size_t)r * 32 + c * 4);
    }
    CP_COMMIT();

    float oacc[8][4];
    float m0 = -1e30f, m1 = -1e30f, l0 = 0.0f, l1 = 0.0f;
#pragma unroll
    for (int n = 0; n < 8; n++)
#pragma unroll
        for (int j = 0; j < 4; j++) oacc[n][j] = 0.0f;

    for (int kb = 0; kb < ntiles; kb++) {
        const int n0 = kb * BN;

        __syncthreads();   // V readers + next-K-buffer readers done

        // Prefetch V(kb)
        for (int i = tid; i < BN * 16; i += THREADS) {
            int r = i >> 4, c = i & 15;
            cpa16(sV_u + (uint32_t)(r * VSTR + c * 4) * 4, Vtg + (size_t)(n0 + r) * DHEAD + c * 4);
        }
        CP_COMMIT();

        // Prefetch K(kb+1) into alternate stage (uniform; clamped on last iter)
        {
            const uint32_t kbase = sK_u + (uint32_t)(((kb + 1) & 1) * 4608) * 4;
            const int n1 = (kb + 1 < ntiles) ? (n0 + BN) : (SEQ - BN);
            for (int i = tid; i < BN * 8; i += THREADS) {
                int r = i >> 3, c = i & 7;
                cpa16(kbase + (uint32_t)(r * QSTR + c * 4) * 4,        Kbg + (size_t)(n1 + r) * 32 + c * 4);
                cpa16(kbase + (uint32_t)(2304 + r * QSTR + c * 4) * 4, Ksg + (size_t)(n1 + r) * 32 + c * 4);
            }
            CP_COMMIT();
        }

        CP_WAIT(2);        // K(kb) landed
        __syncthreads();

        const uint32_t kstage = sK_u + (uint32_t)((kb & 1) * 4608) * 4;

        // ---- S = Q K^T via bf16x3: q1k1 + q1k2 + q2k1 (ldmatrix operands) ----
        float sacc[8][4];
#pragma unroll
        for (int n = 0; n < 8; n++)
#pragma unroll
            for (int j = 0; j < 4; j++) sacc[n][j] = 0.0f;

#pragma unroll
        for (int s = 0; s < 4; s++) {
            uint32_t qfs[4];
            ldsm4(qfs[0], qfs[1], qfs[2], qfs[3], sQs_u + qoff + s * 32);
#pragma unroll
            for (int n = 0; n < 8; n++) {
                uint32_t b0, b1, b2, b3;   // Kb-lo, Kb-hi, Ks-lo, Ks-hi
                ldsm4(b0, b1, b2, b3, kstage + boff + (uint32_t)(n * (8 * QSTR * 4) + s * 32));
                mma16(sacc[n], qfb[s], b0, b1);
                mma16(sacc[n], qfb[s], b2, b3);
                mma16(sacc[n], qfs,    b0, b1);
            }
        }

        // ---- Causal mask (last two key tiles intersect the 128-row diagonal) ----
        if (kb >= ntiles - 2) {
            const int rq = q0 + wid * 16 + g;
#pragma unroll
            for (int n = 0; n < 8; n++) {
                int c = n0 + 8 * n + 2 * q;
                if (c     > rq)     sacc[n][0] = -1e30f;
                if (c + 1 > rq)     sacc[n][1] = -1e30f;
                if (c     > rq + 8) sacc[n][2] = -1e30f;
                if (c + 1 > rq + 8) sacc[n][3] = -1e30f;
            }
        }

        // ---- Online softmax (log2 units) ----
        float mx0 = sacc[0][0], mx1 = sacc[0][2];
#pragma unroll
        for (int n = 0; n < 8; n++) {
            mx0 = fmaxf(mx0, fmaxf(sacc[n][0], sacc[n][1]));
            mx1 = fmaxf(mx1, fmaxf(sacc[n][2], sacc[n][3]));
        }
        mx0 = fmaxf(mx0, __shfl_xor_sync(0xffffffffu, mx0, 1, 4));
        mx0 = fmaxf(mx0, __shfl_xor_sync(0xffffffffu, mx0, 2, 4));
        mx1 = fmaxf(mx1, __shfl_xor_sync(0xffffffffu, mx1, 1, 4));
        mx1 = fmaxf(mx1, __shfl_xor_sync(0xffffffffu, mx1, 2, 4));

        float mn0 = fmaxf(m0, mx0), mn1 = fmaxf(m1, mx1);
        float sc0 = ex2f(m0 - mn0), sc1 = ex2f(m1 - mn1);
        m0 = mn0; m1 = mn1;

        float sum0 = 0.0f, sum1 = 0.0f;
#pragma unroll
        for (int n = 0; n < 8; n++) {
            float p0 = ex2f(sacc[n][0] - m0);
            float p1 = ex2f(sacc[n][1] - m0);
            float p2 = ex2f(sacc[n][2] - m1);
            float p3 = ex2f(sacc[n][3] - m1);
            sum0 += p0 + p1;
            sum1 += p2 + p3;
            float2 w0 = make_float2(__uint_as_float(f2tf32(p0)), __uint_as_float(f2tf32(p1)));
            float2 w1 = make_float2(__uint_as_float(f2tf32(p2)), __uint_as_float(f2tf32(p3)));
            *((float2*)&sPw[(g)     * PSTR + 8 * n + 2 * q]) = w0;
            *((float2*)&sPw[(g + 8) * PSTR + 8 * n + 2 * q]) = w1;
        }
        sum0 += __shfl_xor_sync(0xffffffffu, sum0, 1, 4);
        sum0 += __shfl_xor_sync(0xffffffffu, sum0, 2, 4);
        sum1 += __shfl_xor_sync(0xffffffffu, sum1, 1, 4);
        sum1 += __shfl_xor_sync(0xffffffffu, sum1, 2, 4);
        l0 = l0 * sc0 + sum0;
        l1 = l1 * sc1 + sum1;

#pragma unroll
        for (int n = 0; n < 8; n++) {
            oacc[n][0] *= sc0; oacc[n][1] *= sc0;
            oacc[n][2] *= sc1; oacc[n][3] *= sc1;
        }
        __syncwarp();

        CP_WAIT(1);        // V(kb) landed (K(kb+1) may still be in flight)
        __syncthreads();

        // ---- O += P V (tf32; V pre-rounded rna in gmem scratch) ----
#pragma unroll
        for (int s = 0; s < 8; s++) {
            const int k0 = 8 * s;
            uint32_t pf[4];
            pf[0] = *(const uint32_t*)&sPw[(g)     * PSTR + k0 + q];
            pf[1] = *(const uint32_t*)&sPw[(g + 8) * PSTR + k0 + q];
            pf[2] = *(const uint32_t*)&sPw[(g)     * PSTR + k0 + 4 + q];
            pf[3] = *(const uint32_t*)&sPw[(g + 8) * PSTR + k0 + 4 + q];
#pragma unroll
            for (int n = 0; n < 8; n++) {
                uint32_t v0 = *(const uint32_t*)&sV[(k0 + q)     * VSTR + 8 * n + g];
                uint32_t v1 = *(const uint32_t*)&sV[(k0 + 4 + q) * VSTR + 8 * n + g];
                mma8(oacc[n], pf, v0, v1);
            }
        }
    }

    // ---- Epilogue ----
    const int rq = q0 + wid * 16 + g;
    float inv0 = 1.0f / l0, inv1 = 1.0f / l1;
#pragma unroll
    for (int n = 0; n < 8; n++) {
        *((float2*)&Oh[(size_t)(rq)     * DHEAD + 8 * n + 2 * q]) =
            make_float2(oacc[n][0] * inv0, oacc[n][1] * inv0);
        *((float2*)&Oh[(size_t)(rq + 8) * DHEAD + 8 * n + 2 * q]) =
            make_float2(oacc[n][2] * inv1, oacc[n][3] * inv1);
    }
}

// ---------------------------------------------------------------------------
extern "C" void kernel_launch(void* const* d_in, const int* in_sizes, int n_in,
                              void* d_out, int out_size) {
    const float* Q = (const float*)d_in[0];
    const float* K = (const float*)d_in[1];
    const float* V = (const float*)d_in[2];
    float*       O = (float*)d_out;

    const int total_pairs = ELEMS / 2;
    rope_split_kernel<<<(total_pairs + 255) / 256, 256>>>(Q, K, V, total_pairs);

    size_t smem_bytes =
        (size_t)(2 * 4608 + BM * QSTR) * sizeof(uint32_t) +        // K stages + Qs
        (size_t)(BN * VSTR + NWARP * 16 * PSTR) * sizeof(float);   // V + P
    cudaFuncSetAttribute(attn_kernel, cudaFuncAttributeMaxDynamicSharedMemorySize,
                         (int)smem_bytes);
    dim3 grid(SEQ / BM, NHEADS);
    attn_kernel<<<grid, THREADS, smem_bytes>>>(O);
}